// round 8
// baseline (speedup 1.0000x reference)
#include <cuda_runtime.h>
#include <cstdint>

#define HD   19      // hidden size
#define HJ   20      // padded hidden
#define DD   64      // input size
#define TPB  128
#define RPT  2       // batch rows per thread
#define RPB  (TPB * RPT)   // 256 rows per block
#define NPART 1024

__device__ float g_partials[NPART];

struct Tables {
    float WiT[DD * HJ];   // [k][j] = Wi[j][k]
    float WrT[HD * HJ];   // [k][j] = Wr[j][k]
    float WoT[HD * HJ];   // [k][j] = Wo[j][k]
    float bi[HJ];
    float bo[HJ];
    float bdt[HJ];        // dt / tau_dyn, pad = 0
};
__device__ Tables g_tab;
#define TAB_F ((int)(sizeof(Tables) / 4))

static __device__ __forceinline__ float tanha(float v) {
    float r; asm("tanh.approx.f32 %0,%1;" : "=f"(r) : "f"(v)); return r;
}

// ---------- kernel A: per-block partial sums of |x| ----------
__global__ void __launch_bounds__(256) k_a_red(const float4* __restrict__ x, int n4) {
    float s = 0.f;
    for (int i = blockIdx.x * blockDim.x + threadIdx.x; i < n4;
         i += gridDim.x * blockDim.x) {
        float4 v = x[i];
        s += fabsf(v.x) + fabsf(v.y) + fabsf(v.z) + fabsf(v.w);
    }
#pragma unroll
    for (int o = 16; o > 0; o >>= 1) s += __shfl_down_sync(0xffffffffu, s, o);
    __shared__ float ws[8];
    int w = threadIdx.x >> 5, l = threadIdx.x & 31;
    if (l == 0) ws[w] = s;
    __syncthreads();
    if (threadIdx.x == 0) {
        float t = 0.f;
#pragma unroll
        for (int i = 0; i < 8; i++) t += ws[i];
        g_partials[blockIdx.x] = t;
    }
}

// ---------- kernel B: finish reduction + build transposed tables ----------
__global__ void __launch_bounds__(256) k_prep(
    const float* __restrict__ Wi, const float* __restrict__ bi,
    const float* __restrict__ Wr, const float* __restrict__ Wo,
    const float* __restrict__ bo, const float* __restrict__ tau,
    const float* __restrict__ ta, float invN)
{
    __shared__ float red[256];
    __shared__ float urg_s;
    int t = threadIdx.x;

    float s = 0.f;
    for (int i = t; i < NPART; i += 256) s += g_partials[i];
    red[t] = s;
    __syncthreads();
#pragma unroll
    for (int o = 128; o > 0; o >>= 1) {
        if (t < o) red[t] += red[t + o];
        __syncthreads();
    }
    if (t == 0) urg_s = fmaxf(red[0] * invN, 0.01f);

    float* gt = (float*)&g_tab;
    for (int i = t; i < TAB_F; i += 256) gt[i] = 0.f;
    __syncthreads();
    float urg = urg_s;

    for (int i = t; i < DD * HD; i += 256) {
        int k = i / HD, j = i % HD;
        g_tab.WiT[k * HJ + j] = Wi[j * DD + k];
    }
    for (int i = t; i < HD * HD; i += 256) {
        int k = i / HD, j = i % HD;
        g_tab.WrT[k * HJ + j] = Wr[j * HD + k];
        g_tab.WoT[k * HJ + j] = Wo[j * HD + k];
    }
    if (t < HD) {
        g_tab.bi[t] = bi[t];
        g_tab.bo[t] = bo[t];
        float td = tau[t] * (1.0f - ta[t]) + ta[t] / urg;
        td = fminf(fmaxf(td, 0.01f), 10.0f);
        g_tab.bdt[t] = 0.01f / td;
    }
}

// ---------- kernel C: fused mapped + recurrence + output, scalar, 2 rows/thread ----------
__global__ void __launch_bounds__(TPB, 4)
k_main(const float* __restrict__ x, const int* __restrict__ steps_p,
       float* __restrict__ out, float* __restrict__ hout)
{
    __shared__ float sWi[DD * HJ];     // 1280
    __shared__ float sWr[HD * HJ];     // 380
    __shared__ float sWo[HD * HJ];     // 380
    __shared__ float sBi[HJ], sBo[HJ], sBd[HJ];
    __shared__ float mst[HJ * RPB];    // mapped, [j][row]; reused as out staging

    const int tid = threadIdx.x;
    {
        const float* gt = (const float*)&g_tab;
        for (int i = tid; i < DD * HJ; i += TPB) sWi[i] = gt[i];
        const float* g2 = gt + DD * HJ;
        for (int i = tid; i < 2 * HD * HJ + 3 * HJ; i += TPB) {
            // contiguous: WrT, WoT, bi, bo, bdt
            float v = g2[i];
            if (i < HD * HJ) sWr[i] = v;
            else if (i < 2 * HD * HJ) sWo[i - HD * HJ] = v;
            else {
                int r = i - 2 * HD * HJ;
                if (r < HJ) sBi[r] = v;
                else if (r < 2 * HJ) sBo[r - HJ] = v;
                else sBd[r - 2 * HJ] = v;
            }
        }
    }
    __syncthreads();

    // ---- phase 1: mapped = x @ Wi^T + bi (each row sequentially) ----
    for (int r = 0; r < RPT; r++) {
        const float4* xr = (const float4*)(x +
            ((size_t)blockIdx.x * RPB + r * TPB + tid) * DD);
        float m[HD];
#pragma unroll
        for (int j = 0; j < HD; j++) m[j] = sBi[j];
#pragma unroll 4
        for (int q = 0; q < DD / 4; q++) {
            float4 v = xr[q];
            float vv[4] = {v.x, v.y, v.z, v.w};
#pragma unroll
            for (int e = 0; e < 4; e++) {
                const float* w = &sWi[(q * 4 + e) * HJ];
                float xk = vv[e];
#pragma unroll
                for (int j = 0; j < HD; j++) m[j] = fmaf(xk, w[j], m[j]);
            }
        }
#pragma unroll
        for (int j = 0; j < HD; j++) mst[j * RPB + r * TPB + tid] = m[j];
    }
    __syncthreads();

    // ---- phase 2: recurrence, 2 rows/thread sharing weight loads ----
    float h0[HD], h1[HD];
#pragma unroll
    for (int j = 0; j < HD; j++) { h0[j] = 0.f; h1[j] = 0.f; }

    const int steps = *steps_p;
    for (int s = 0; s < steps; s++) {
        float a0[HD], a1[HD];
#pragma unroll
        for (int j = 0; j < HD; j++) {
            a0[j] = mst[j * RPB + tid];
            a1[j] = mst[j * RPB + TPB + tid];
        }
#pragma unroll
        for (int k = 0; k < HD; k++) {
            const float* w = &sWr[k * HJ];
            float hk0 = h0[k], hk1 = h1[k];
#pragma unroll
            for (int j = 0; j < HD; j++) {
                float wv = w[j];
                a0[j] = fmaf(hk0, wv, a0[j]);
                a1[j] = fmaf(hk1, wv, a1[j]);
            }
        }
#pragma unroll
        for (int j = 0; j < HD; j++) {
            float b = sBd[j];
            h0[j] = fmaf(b, tanha(a0[j]) - h0[j], h0[j]);
            h1[j] = fmaf(b, tanha(a1[j]) - h1[j], h1[j]);
        }
    }

    // ---- phase 3: out = h @ Wo^T + bo ----
    float o0[HD], o1[HD];
#pragma unroll
    for (int j = 0; j < HD; j++) { o0[j] = sBo[j]; o1[j] = sBo[j]; }
#pragma unroll
    for (int k = 0; k < HD; k++) {
        const float* w = &sWo[k * HJ];
        float hk0 = h0[k], hk1 = h1[k];
#pragma unroll
        for (int j = 0; j < HD; j++) {
            float wv = w[j];
            o0[j] = fmaf(hk0, wv, o0[j]);
            o1[j] = fmaf(hk1, wv, o1[j]);
        }
    }

    // ---- stage + coalesced stores (mst reused: need 4864 <= 5120 floats) ----
    __syncthreads();
    float* f = mst;
#pragma unroll
    for (int j = 0; j < HD; j++) {
        f[(tid) * HD + j]       = o0[j];
        f[(TPB + tid) * HD + j] = o1[j];
    }
    __syncthreads();
    {
        float4* go = (float4*)(out + (size_t)blockIdx.x * (RPB * HD));
        const float4* f4 = (const float4*)f;
        for (int i = tid; i < RPB * HD / 4; i += TPB) go[i] = f4[i];
    }
    if (hout) {
        __syncthreads();
#pragma unroll
        for (int j = 0; j < HD; j++) {
            f[(tid) * HD + j]       = h0[j];
            f[(TPB + tid) * HD + j] = h1[j];
        }
        __syncthreads();
        float4* gh = (float4*)(hout + (size_t)blockIdx.x * (RPB * HD));
        const float4* f4 = (const float4*)f;
        for (int i = tid; i < RPB * HD / 4; i += TPB) gh[i] = f4[i];
    }
}

extern "C" void kernel_launch(void* const* d_in, const int* in_sizes, int n_in,
                              void* d_out, int out_size) {
    const float* x   = (const float*)d_in[0];
    const float* Wi  = (const float*)d_in[1];
    const float* bi  = (const float*)d_in[2];
    const float* Wr  = (const float*)d_in[3];
    const float* Wo  = (const float*)d_in[4];
    const float* bo  = (const float*)d_in[5];
    const float* tau = (const float*)d_in[6];
    const float* ta  = (const float*)d_in[7];
    const int* steps = (const int*)d_in[8];

    const int nx = in_sizes[0];
    const int B  = nx / DD;

    float* out = (float*)d_out;
    long long bh = (long long)B * HD;
    float* hout = ((long long)out_size >= 2 * bh) ? (out + bh) : nullptr;

    k_a_red<<<NPART, 256>>>((const float4*)x, nx / 4);
    k_prep<<<1, 256>>>(Wi, bi, Wr, Wo, bo, tau, ta, 1.0f / (float)nx);
    k_main<<<B / RPB, TPB>>>(x, steps, out, hout);
}